// round 14
// baseline (speedup 1.0000x reference)
#include <cuda_runtime.h>
#include <cuda_bf16.h>
#include <math.h>
#include <stdint.h>

// ---------------------------------------------------------------------------
// Problem constants
//   b=16, s=512, d=2048, H=16 heads, hd=128, G=4 kv groups, P=4 heads/group
// ---------------------------------------------------------------------------
#define BB 16
#define SS 512
#define DD 2048
#define NH 16
#define HD 128
#define NG 4
#define MROWS (BB * SS)          // 8192
#define KVD (NG * HD)            // 512

// Scratch (device globals: allocation-free rule)
__device__ float g_q[MROWS * DD];          // (b,s,H,hd) = 64MB
__device__ float g_k[MROWS * KVD];         // 16MB
__device__ float g_v[MROWS * KVD];         // 16MB
__device__ float g_ctx[MROWS * DD];        // 64MB

// ---------------------------------------------------------------------------
// tf32 helpers (compile+run proven on this harness)
// ---------------------------------------------------------------------------
__device__ __forceinline__ uint32_t f2tf32(float f) {
    uint32_t u;
    asm("cvt.rna.tf32.f32 %0, %1;" : "=r"(u) : "f"(f));
    return u;
}

__device__ __forceinline__ void mma1688(float* c, const uint32_t* a, const uint32_t* b) {
    asm volatile(
        "mma.sync.aligned.m16n8k8.row.col.f32.tf32.tf32.f32 "
        "{%0,%1,%2,%3}, {%4,%5,%6,%7}, {%8,%9}, {%0,%1,%2,%3};"
        : "+f"(c[0]), "+f"(c[1]), "+f"(c[2]), "+f"(c[3])
        : "r"(a[0]), "r"(a[1]), "r"(a[2]), "r"(a[3]), "r"(b[0]), "r"(b[1]));
}

__device__ __forceinline__ uint32_t smem_u32(const void* p) {
    uint32_t a;
    asm("{ .reg .u64 t; cvta.to.shared.u64 t, %1; cvt.u32.u64 %0, t; }"
        : "=r"(a) : "l"(p));
    return a;
}

__device__ __forceinline__ void cp_async16(uint32_t dst, const void* src) {
    asm volatile("cp.async.cg.shared.global [%0], [%1], 16;"
                 :: "r"(dst), "l"(src));
}
#define CP_COMMIT()  asm volatile("cp.async.commit_group;" ::: "memory")
#define CP_WAIT(n)   asm volatile("cp.async.wait_group %0;" :: "n"(n) : "memory")

// ---------------------------------------------------------------------------
// TF32 tensor-core GEMM: C[M,N] = A[M,K] @ W[K,N] + bias[N]  (all row-major)
// W is used UNTRANSPOSED (staged n-contiguous per k-row).
// Block tile 128x128, BK=16, 256 threads (8 warps as 2x4), warp tile 64x32.
// A smem [128][20]  (stride 20 -> conflict-free scalar fragment LDS)
// B smem [16][136]  (stride 136 -> conflict-free scalar fragment LDS)
// 4-stage cp.async pipeline (prefetch distance 3), one syncthreads/chunk.
// M%128==0, N%128==0, K%16==0 and K/16 >= 3 for all calls.
// ---------------------------------------------------------------------------
#define ALD 20
#define BLD 136
#define GSTAGES 4
#define A_BYTES (128 * ALD * 4)                    // 10240
#define B_BYTES (16 * BLD * 4)                     // 8704
#define GEMM_SMEM (GSTAGES * (A_BYTES + B_BYTES))  // 75776

__global__ __launch_bounds__(256, 2)
void tf32_gemm(const float* __restrict__ A, const float* __restrict__ W,
               const float* __restrict__ bias, float* __restrict__ C,
               int M, int N, int K)
{
    extern __shared__ char gsm[];
    const uint32_t smb = smem_u32(gsm);

    const int tid  = threadIdx.x;
    const int lane = tid & 31;
    const int w    = tid >> 5;
    const int wm   = w >> 2;            // 0..1 (M dir, 64 rows)
    const int wn   = w & 3;             // 0..3 (N dir, 32 cols)
    const int g    = lane >> 2;         // mma groupID 0..7
    const int t    = lane & 3;          // mma thread-in-group 0..3
    const int m0   = blockIdx.y << 7;
    const int n0   = blockIdx.x << 7;

    // ---- staging maps ----
    // A: row sr (0..127), two float4 at cols sc, sc+4 (sc in {0,8})
    const int a_sr = tid >> 1;
    const int a_sc = (tid & 1) << 3;
    const float* Ag = A + (size_t)(m0 + a_sr) * K + a_sc;
    const uint32_t a_dst0 = smb + (uint32_t)(a_sr * ALD + a_sc) * 4u;
    // B: k-row kr (0..15), two float4 at cols bc, bc+4 (bc = (tid&15)*8)
    const int b_kr = tid >> 4;
    const int b_bc = (tid & 15) << 3;
    const float* Bg = W + (size_t)b_kr * N + n0 + b_bc;
    const uint32_t b_dst0 = smb + GSTAGES * A_BYTES + (uint32_t)(b_kr * BLD + b_bc) * 4u;

    const float* Abase = (const float*)gsm;
    const float* Bbase = (const float*)(gsm + GSTAGES * A_BYTES);

    float acc[4][4][4];
#pragma unroll
    for (int i = 0; i < 4; ++i)
#pragma unroll
        for (int j = 0; j < 4; ++j)
#pragma unroll
            for (int r = 0; r < 4; ++r) acc[i][j][r] = 0.f;

    const int NC = K >> 4;              // always >= 32 here

    // prologue: chunks 0..2 into stages 0..2
#pragma unroll
    for (int p = 0; p < 3; ++p) {
        const int k0 = p << 4;
        const uint32_t ad = a_dst0 + p * A_BYTES;
        const uint32_t bd = b_dst0 + p * B_BYTES;
        cp_async16(ad,      Ag + k0);
        cp_async16(ad + 16, Ag + k0 + 4);
        cp_async16(bd,      Bg + (size_t)k0 * N);
        cp_async16(bd + 16, Bg + (size_t)k0 * N + 4);
        CP_COMMIT();
    }

    for (int c = 0; c < NC; ++c) {
        CP_WAIT(2);            // chunk c's group complete (<=2 younger pending)
        __syncthreads();       // all threads past chunk c-1 compute; loads visible

        if (c + 3 < NC) {      // prefetch chunk c+3 into stage (c+3)&3
            const int k0 = (c + 3) << 4;
            const int s  = (c + 3) & 3;
            const uint32_t ad = a_dst0 + s * A_BYTES;
            const uint32_t bd = b_dst0 + s * B_BYTES;
            cp_async16(ad,      Ag + k0);
            cp_async16(ad + 16, Ag + k0 + 4);
            cp_async16(bd,      Bg + (size_t)k0 * N);
            cp_async16(bd + 16, Bg + (size_t)k0 * N + 4);
        }
        CP_COMMIT();           // empty groups near tail keep accounting valid

        const float* Ab = Abase + (c & 3) * (128 * ALD);
        const float* Bb = Bbase + (c & 3) * (16 * BLD);
#pragma unroll
        for (int ks = 0; ks < 2; ++ks) {
            const int kb = ks * 8 + t;
            uint32_t af[4][4], bf[4][2];
#pragma unroll
            for (int i = 0; i < 4; ++i) {
                const int r = wm * 64 + i * 16 + g;
                af[i][0] = f2tf32(Ab[r * ALD + kb]);
                af[i][1] = f2tf32(Ab[(r + 8) * ALD + kb]);
                af[i][2] = f2tf32(Ab[r * ALD + kb + 4]);
                af[i][3] = f2tf32(Ab[(r + 8) * ALD + kb + 4]);
            }
#pragma unroll
            for (int j = 0; j < 4; ++j) {
                const int n = wn * 32 + j * 8 + g;
                bf[j][0] = f2tf32(Bb[kb * BLD + n]);
                bf[j][1] = f2tf32(Bb[(kb + 4) * BLD + n]);
            }
#pragma unroll
            for (int i = 0; i < 4; ++i)
#pragma unroll
                for (int j = 0; j < 4; ++j)
                    mma1688(acc[i][j], af[i], bf[j]);
        }
    }

    // epilogue: bias + store (c0,c1 -> row g cols 2t,2t+1; c2,c3 -> row g+8)
#pragma unroll
    for (int j = 0; j < 4; ++j) {
        const int col = n0 + wn * 32 + j * 8 + t * 2;
        const float2 bs = *(const float2*)&bias[col];
#pragma unroll
        for (int i = 0; i < 4; ++i) {
            const int row = m0 + wm * 64 + i * 16 + g;
            float2 v0, v1;
            v0.x = acc[i][j][0] + bs.x; v0.y = acc[i][j][1] + bs.y;
            v1.x = acc[i][j][2] + bs.x; v1.y = acc[i][j][3] + bs.y;
            *(float2*)&C[(size_t)row * N + col]       = v0;
            *(float2*)&C[(size_t)(row + 8) * N + col] = v1;
        }
    }
}

// ---------------------------------------------------------------------------
// RMSNorm + RoPE (unchanged, passing)
// ---------------------------------------------------------------------------
__global__ __launch_bounds__(256)
void norm_rope_kernel(float* __restrict__ X, const float* __restrict__ scale,
                      int nh, float extra)
{
    const int warp = threadIdx.x >> 5;
    const int lane = threadIdx.x & 31;
    const int row  = blockIdx.x * 8 + warp;
    const int t    = (row / nh) & (SS - 1);

    float* p = X + (size_t)row * HD + lane * 4;
    float4 v = *(float4*)p;

    float ss = v.x * v.x + v.y * v.y + v.z * v.z + v.w * v.w;
#pragma unroll
    for (int o = 16; o; o >>= 1) ss += __shfl_xor_sync(0xffffffffu, ss, o);
    const float r = rsqrtf(ss * (1.0f / 128.0f) + 1e-6f);

    float4 sc = *(const float4*)(scale + lane * 4);
    float y0 = v.x * r * sc.x;
    float y1 = v.y * r * sc.y;
    float y2 = v.z * r * sc.z;
    float y3 = v.w * r * sc.w;

    const int i0 = lane * 2;
    const float LN1E4 = 9.2103403719761836f;
    float f0 = expf(-((float)(2 * i0)     * (1.0f / 128.0f)) * LN1E4);
    float f1 = expf(-((float)(2 * i0 + 2) * (1.0f / 128.0f)) * LN1E4);
    float s0, c0, s1, c1;
    sincosf((float)t * f0, &s0, &c0);
    sincosf((float)t * f1, &s1, &c1);

    float4 o;
    o.x = (y0 * c0 - y1 * s0) * extra;
    o.y = (y0 * s0 + y1 * c0) * extra;
    o.z = (y2 * c1 - y3 * s1) * extra;
    o.w = (y2 * s1 + y3 * c1) * extra;
    *(float4*)p = o;
}

// ---------------------------------------------------------------------------
// Causal flash attention, fp32 (unchanged, passing)
// ---------------------------------------------------------------------------
#define QS_LD 129
#define PS_LD 68
#define ATTN_SMEM ((2 * 64 * QS_LD + 64 * PS_LD) * 4)   // 83456 bytes

__global__ __launch_bounds__(256)
void attn_kernel(const float* __restrict__ Q, const float* __restrict__ Kg,
                 const float* __restrict__ Vg, float* __restrict__ ctx)
{
    extern __shared__ float smf[];
    float* Qs = smf;
    float* Ks = smf + 64 * QS_LD;
    float* Ps = smf + 2 * 64 * QS_LD;

    const int tid = threadIdx.x;
    const int tx  = tid & 15;
    const int ty  = tid >> 4;
    const int q0  = blockIdx.x << 6;
    const int h   = blockIdx.y;
    const int b   = blockIdx.z;
    const int g   = h >> 2;

    for (int f = tid; f < 2048; f += 256) {
        const int r = f >> 5, c = (f & 31) << 2;
        float4 v = *(const float4*)(Q + ((size_t)((b * SS + q0 + r) * NH + h)) * HD + c);
        float* d = Qs + r * QS_LD + c;
        d[0] = v.x; d[1] = v.y; d[2] = v.z; d[3] = v.w;
    }

    float m_run[4], l_run[4], Ob[4][8];
#pragma unroll
    for (int i = 0; i < 4; ++i) {
        m_run[i] = -1e30f; l_run[i] = 0.f;
#pragma unroll
        for (int c = 0; c < 8; ++c) Ob[i][c] = 0.f;
    }

    const float* q_r0 = Qs + (ty * 4 + 0) * QS_LD;
    const float* q_r1 = Qs + (ty * 4 + 1) * QS_LD;
    const float* q_r2 = Qs + (ty * 4 + 2) * QS_LD;
    const float* q_r3 = Qs + (ty * 4 + 3) * QS_LD;
    const float* k_r0 = Ks + (tx * 4 + 0) * QS_LD;
    const float* k_r1 = Ks + (tx * 4 + 1) * QS_LD;
    const float* k_r2 = Ks + (tx * 4 + 2) * QS_LD;
    const float* k_r3 = Ks + (tx * 4 + 3) * QS_LD;

    for (int j0 = 0; j0 <= q0; j0 += 64) {
        __syncthreads();
        for (int f = tid; f < 2048; f += 256) {
            const int r = f >> 5, c = (f & 31) << 2;
            float4 v = *(const float4*)(Kg + ((size_t)((b * SS + j0 + r) * NG + g)) * HD + c);
            float* d = Ks + r * QS_LD + c;
            d[0] = v.x; d[1] = v.y; d[2] = v.z; d[3] = v.w;
        }
        __syncthreads();

        float acc[4][4];
#pragma unroll
        for (int i = 0; i < 4; ++i)
#pragma unroll
            for (int j = 0; j < 4; ++j) acc[i][j] = 0.f;

#pragma unroll 4
        for (int d = 0; d < HD; ++d) {
            const float a0 = q_r0[d], a1 = q_r1[d], a2 = q_r2[d], a3 = q_r3[d];
            const float b0 = k_r0[d], b1 = k_r1[d], b2 = k_r2[d], b3 = k_r3[d];
            acc[0][0] = fmaf(a0, b0, acc[0][0]); acc[0][1] = fmaf(a0, b1, acc[0][1]);
            acc[0][2] = fmaf(a0, b2, acc[0][2]); acc[0][3] = fmaf(a0, b3, acc[0][3]);
            acc[1][0] = fmaf(a1, b0, acc[1][0]); acc[1][1] = fmaf(a1, b1, acc[1][1]);
            acc[1][2] = fmaf(a1, b2, acc[1][2]); acc[1][3] = fmaf(a1, b3, acc[1][3]);
            acc[2][0] = fmaf(a2, b0, acc[2][0]); acc[2][1] = fmaf(a2, b1, acc[2][1]);
            acc[2][2] = fmaf(a2, b2, acc[2][2]); acc[2][3] = fmaf(a2, b3, acc[2][3]);
            acc[3][0] = fmaf(a3, b0, acc[3][0]); acc[3][1] = fmaf(a3, b1, acc[3][1]);
            acc[3][2] = fmaf(a3, b2, acc[3][2]); acc[3][3] = fmaf(a3, b3, acc[3][3]);
        }

        if (j0 == q0) {
#pragma unroll
            for (int i = 0; i < 4; ++i)
#pragma unroll
                for (int j = 0; j < 4; ++j)
                    if (tx * 4 + j > ty * 4 + i) acc[i][j] = -1e30f;
        }

#pragma unroll
        for (int i = 0; i < 4; ++i) {
            float mx = fmaxf(fmaxf(acc[i][0], acc[i][1]), fmaxf(acc[i][2], acc[i][3]));
#pragma unroll
            for (int o = 8; o; o >>= 1)
                mx = fmaxf(mx, __shfl_xor_sync(0xffffffffu, mx, o, 16));
            const float mnew = fmaxf(m_run[i], mx);
            const float corr = __expf(m_run[i] - mnew);
            float rs = 0.f;
#pragma unroll
            for (int j = 0; j < 4; ++j) {
                const float p = __expf(acc[i][j] - mnew);
                acc[i][j] = p; rs += p;
            }
#pragma unroll
            for (int o = 8; o; o >>= 1)
                rs += __shfl_xor_sync(0xffffffffu, rs, o, 16);
            l_run[i] = l_run[i] * corr + rs;
            m_run[i] = mnew;
#pragma unroll
            for (int c = 0; c < 8; ++c) Ob[i][c] *= corr;
            float* pp = Ps + (ty * 4 + i) * PS_LD + tx * 4;
            pp[0] = acc[i][0]; pp[1] = acc[i][1];
            pp[2] = acc[i][2]; pp[3] = acc[i][3];
        }
        __syncthreads();

        for (int f = tid; f < 2048; f += 256) {
            const int r = f >> 5, c = (f & 31) << 2;
            float4 v = *(const float4*)(Vg + ((size_t)((b * SS + j0 + r) * NG + g)) * HD + c);
            float* d = Ks + r * QS_LD + c;
            d[0] = v.x; d[1] = v.y; d[2] = v.z; d[3] = v.w;
        }
        __syncthreads();

        const float* p_r0 = Ps + (ty * 4 + 0) * PS_LD;
        const float* p_r1 = Ps + (ty * 4 + 1) * PS_LD;
        const float* p_r2 = Ps + (ty * 4 + 2) * PS_LD;
        const float* p_r3 = Ps + (ty * 4 + 3) * PS_LD;
#pragma unroll 2
        for (int j = 0; j < 64; ++j) {
            const float a0 = p_r0[j], a1 = p_r1[j], a2 = p_r2[j], a3 = p_r3[j];
            const float* vrow = Ks + j * QS_LD + tx;
#pragma unroll
            for (int c = 0; c < 8; ++c) {
                const float vv = vrow[c << 4];
                Ob[0][c] = fmaf(a0, vv, Ob[0][c]);
                Ob[1][c] = fmaf(a1, vv, Ob[1][c]);
                Ob[2][c] = fmaf(a2, vv, Ob[2][c]);
                Ob[3][c] = fmaf(a3, vv, Ob[3][c]);
            }
        }
    }

#pragma unroll
    for (int i = 0; i < 4; ++i) {
        const float inv = 1.0f / l_run[i];
        float* base = ctx + ((size_t)((b * SS + q0 + ty * 4 + i) * NH + h)) * HD + tx;
#pragma unroll
        for (int c = 0; c < 8; ++c) base[c << 4] = Ob[i][c] * inv;
    }
}

// ---------------------------------------------------------------------------
// kernel_launch
// ---------------------------------------------------------------------------
extern "C" void kernel_launch(void* const* d_in, const int* in_sizes, int n_in,
                              void* d_out, int out_size)
{
    (void)in_sizes; (void)n_in; (void)out_size;
    const float* x  = (const float*)d_in[0];
    const float* Wq = (const float*)d_in[1];
    const float* bq = (const float*)d_in[2];
    const float* Wk = (const float*)d_in[3];
    const float* bk = (const float*)d_in[4];
    const float* Wv = (const float*)d_in[5];
    const float* bv = (const float*)d_in[6];
    const float* Wo = (const float*)d_in[7];
    const float* bo = (const float*)d_in[8];
    const float* q_scale = (const float*)d_in[9];
    const float* k_scale = (const float*)d_in[10];
    float* out = (float*)d_out;

    float *gq, *gk, *gv, *gc;
    cudaGetSymbolAddress((void**)&gq, g_q);
    cudaGetSymbolAddress((void**)&gk, g_k);
    cudaGetSymbolAddress((void**)&gv, g_v);
    cudaGetSymbolAddress((void**)&gc, g_ctx);

    cudaFuncSetAttribute(attn_kernel,
                         cudaFuncAttributeMaxDynamicSharedMemorySize, ATTN_SMEM);
    cudaFuncSetAttribute(tf32_gemm,
                         cudaFuncAttributeMaxDynamicSharedMemorySize, GEMM_SMEM);

    const dim3 blk(256);

    // Projections (tf32 mma, W used untransposed, 4-stage pipeline)
    tf32_gemm<<<dim3(DD / 128, MROWS / 128), blk, GEMM_SMEM>>>(x, Wq, bq, gq, MROWS, DD, DD);
    tf32_gemm<<<dim3(KVD / 128, MROWS / 128), blk, GEMM_SMEM>>>(x, Wk, bk, gk, MROWS, KVD, DD);
    tf32_gemm<<<dim3(KVD / 128, MROWS / 128), blk, GEMM_SMEM>>>(x, Wv, bv, gv, MROWS, KVD, DD);

    // RMSNorm + RoPE (q gets combined 1/hd logit scale folded in)
    norm_rope_kernel<<<(MROWS * NH) / 8, blk>>>(gq, q_scale, NH, 1.0f / 128.0f);
    norm_rope_kernel<<<(MROWS * NG) / 8, blk>>>(gk, k_scale, NG, 1.0f);

    // Causal GQA attention
    attn_kernel<<<dim3(SS / 64, NH, BB), blk, ATTN_SMEM>>>(gq, gk, gv, gc);

    // Output projection
    tf32_gemm<<<dim3(DD / 128, MROWS / 128), blk, GEMM_SMEM>>>(gc, Wo, bo, out, MROWS, DD, DD);
}

// round 15
// speedup vs baseline: 1.3173x; 1.3173x over previous
#include <cuda_runtime.h>
#include <cuda_bf16.h>
#include <math.h>
#include <stdint.h>

// ---------------------------------------------------------------------------
// Problem constants
//   b=16, s=512, d=2048, H=16 heads, hd=128, G=4 kv groups, P=4 heads/group
// ---------------------------------------------------------------------------
#define BB 16
#define SS 512
#define DD 2048
#define NH 16
#define HD 128
#define NG 4
#define MROWS (BB * SS)          // 8192
#define KVD (NG * HD)            // 512

// Scratch (device globals: allocation-free rule)
__device__ float g_q[MROWS * DD];          // (b,s,H,hd) = 64MB
__device__ float g_k[MROWS * KVD];         // 16MB
__device__ float g_v[MROWS * KVD];         // 16MB
__device__ float g_ctx[MROWS * DD];        // 64MB

// ---------------------------------------------------------------------------
// tf32 helpers (compile+run proven on this harness)
// ---------------------------------------------------------------------------
__device__ __forceinline__ uint32_t f2tf32(float f) {
    uint32_t u;
    asm("cvt.rna.tf32.f32 %0, %1;" : "=r"(u) : "f"(f));
    return u;
}

__device__ __forceinline__ void mma1688(float* c, const uint32_t* a, const uint32_t* b) {
    asm volatile(
        "mma.sync.aligned.m16n8k8.row.col.f32.tf32.tf32.f32 "
        "{%0,%1,%2,%3}, {%4,%5,%6,%7}, {%8,%9}, {%0,%1,%2,%3};"
        : "+f"(c[0]), "+f"(c[1]), "+f"(c[2]), "+f"(c[3])
        : "r"(a[0]), "r"(a[1]), "r"(a[2]), "r"(a[3]), "r"(b[0]), "r"(b[1]));
}

__device__ __forceinline__ uint32_t smem_u32(const void* p) {
    uint32_t a;
    asm("{ .reg .u64 t; cvta.to.shared.u64 t, %1; cvt.u32.u64 %0, t; }"
        : "=r"(a) : "l"(p));
    return a;
}

__device__ __forceinline__ void cp_async16(uint32_t dst, const void* src) {
    asm volatile("cp.async.cg.shared.global [%0], [%1], 16;"
                 :: "r"(dst), "l"(src));
}
#define CP_COMMIT()  asm volatile("cp.async.commit_group;" ::: "memory")
#define CP_WAIT(n)   asm volatile("cp.async.wait_group %0;" :: "n"(n) : "memory")

// ---------------------------------------------------------------------------
// TF32 tensor-core GEMM (R13-exact, best measured): C = A @ W + bias.
// Block tile 128x128, BK=16, 256 threads, warp tile 64x32, 2-stage cp.async.
// A smem [128][20], B smem [16][136] -> conflict-free fragment LDS.
// ---------------------------------------------------------------------------
#define ALD 20
#define BLD 136

__global__ __launch_bounds__(256, 2)
void tf32_gemm(const float* __restrict__ A, const float* __restrict__ W,
               const float* __restrict__ bias, float* __restrict__ C,
               int M, int N, int K)
{
    __shared__ float As[2][128 * ALD];   // 2 x 10240B
    __shared__ float Bs[2][16 * BLD];    // 2 x  8704B

    const int tid  = threadIdx.x;
    const int lane = tid & 31;
    const int w    = tid >> 5;
    const int wm   = w >> 2;            // 0..1 (M dir, 64 rows)
    const int wn   = w & 3;             // 0..3 (N dir, 32 cols)
    const int g    = lane >> 2;         // mma groupID 0..7
    const int t    = lane & 3;          // mma thread-in-group 0..3
    const int m0   = blockIdx.y << 7;
    const int n0   = blockIdx.x << 7;

    const int a_sr = tid >> 1;
    const int a_sc = (tid & 1) << 3;
    const float* Ag = A + (size_t)(m0 + a_sr) * K + a_sc;
    const uint32_t a_dst = smem_u32(&As[0][a_sr * ALD + a_sc]);
    const int b_kr = tid >> 4;
    const int b_bc = (tid & 15) << 3;
    const float* Bg = W + (size_t)b_kr * N + n0 + b_bc;
    const uint32_t b_dst = smem_u32(&Bs[0][b_kr * BLD + b_bc]);
    const uint32_t buf_a = 128 * ALD * 4;
    const uint32_t buf_b = 16 * BLD * 4;

    float acc[4][4][4];
#pragma unroll
    for (int i = 0; i < 4; ++i)
#pragma unroll
        for (int j = 0; j < 4; ++j)
#pragma unroll
            for (int r = 0; r < 4; ++r) acc[i][j][r] = 0.f;

    const int NC = K >> 4;

    cp_async16(a_dst,      Ag);
    cp_async16(a_dst + 16, Ag + 4);
    cp_async16(b_dst,      Bg);
    cp_async16(b_dst + 16, Bg + 4);
    CP_COMMIT();

    for (int c = 0; c < NC; ++c) {
        if (c + 1 < NC) {
            const int nb = (c + 1) & 1;
            const int k0 = (c + 1) << 4;
            cp_async16(a_dst + nb * buf_a,      Ag + k0);
            cp_async16(a_dst + nb * buf_a + 16, Ag + k0 + 4);
            cp_async16(b_dst + nb * buf_b,      Bg + (size_t)k0 * N);
            cp_async16(b_dst + nb * buf_b + 16, Bg + (size_t)k0 * N + 4);
            CP_COMMIT();
            CP_WAIT(1);
        } else {
            CP_WAIT(0);
        }
        __syncthreads();

        const float* Ab = As[c & 1];
        const float* Bb = Bs[c & 1];
#pragma unroll
        for (int ks = 0; ks < 2; ++ks) {
            const int kb = ks * 8 + t;
            uint32_t af[4][4], bf[4][2];
#pragma unroll
            for (int i = 0; i < 4; ++i) {
                const int r = wm * 64 + i * 16 + g;
                af[i][0] = f2tf32(Ab[r * ALD + kb]);
                af[i][1] = f2tf32(Ab[(r + 8) * ALD + kb]);
                af[i][2] = f2tf32(Ab[r * ALD + kb + 4]);
                af[i][3] = f2tf32(Ab[(r + 8) * ALD + kb + 4]);
            }
#pragma unroll
            for (int j = 0; j < 4; ++j) {
                const int n = wn * 32 + j * 8 + g;
                bf[j][0] = f2tf32(Bb[kb * BLD + n]);
                bf[j][1] = f2tf32(Bb[(kb + 4) * BLD + n]);
            }
#pragma unroll
            for (int i = 0; i < 4; ++i)
#pragma unroll
                for (int j = 0; j < 4; ++j)
                    mma1688(acc[i][j], af[i], bf[j]);
        }
        __syncthreads();
    }

#pragma unroll
    for (int j = 0; j < 4; ++j) {
        const int col = n0 + wn * 32 + j * 8 + t * 2;
        const float2 bs = *(const float2*)&bias[col];
#pragma unroll
        for (int i = 0; i < 4; ++i) {
            const int row = m0 + wm * 64 + i * 16 + g;
            float2 v0, v1;
            v0.x = acc[i][j][0] + bs.x; v0.y = acc[i][j][1] + bs.y;
            v1.x = acc[i][j][2] + bs.x; v1.y = acc[i][j][3] + bs.y;
            *(float2*)&C[(size_t)row * N + col]       = v0;
            *(float2*)&C[(size_t)(row + 8) * N + col] = v1;
        }
    }
}

// ---------------------------------------------------------------------------
// RMSNorm + RoPE (unchanged, passing)
// ---------------------------------------------------------------------------
__global__ __launch_bounds__(256)
void norm_rope_kernel(float* __restrict__ X, const float* __restrict__ scale,
                      int nh, float extra)
{
    const int warp = threadIdx.x >> 5;
    const int lane = threadIdx.x & 31;
    const int row  = blockIdx.x * 8 + warp;
    const int t    = (row / nh) & (SS - 1);

    float* p = X + (size_t)row * HD + lane * 4;
    float4 v = *(float4*)p;

    float ss = v.x * v.x + v.y * v.y + v.z * v.z + v.w * v.w;
#pragma unroll
    for (int o = 16; o; o >>= 1) ss += __shfl_xor_sync(0xffffffffu, ss, o);
    const float r = rsqrtf(ss * (1.0f / 128.0f) + 1e-6f);

    float4 sc = *(const float4*)(scale + lane * 4);
    float y0 = v.x * r * sc.x;
    float y1 = v.y * r * sc.y;
    float y2 = v.z * r * sc.z;
    float y3 = v.w * r * sc.w;

    const int i0 = lane * 2;
    const float LN1E4 = 9.2103403719761836f;
    float f0 = expf(-((float)(2 * i0)     * (1.0f / 128.0f)) * LN1E4);
    float f1 = expf(-((float)(2 * i0 + 2) * (1.0f / 128.0f)) * LN1E4);
    float s0, c0, s1, c1;
    sincosf((float)t * f0, &s0, &c0);
    sincosf((float)t * f1, &s1, &c1);

    float4 o;
    o.x = (y0 * c0 - y1 * s0) * extra;
    o.y = (y0 * s0 + y1 * c0) * extra;
    o.z = (y2 * c1 - y3 * s1) * extra;
    o.w = (y2 * s1 + y3 * c1) * extra;
    *(float4*)p = o;
}

// ---------------------------------------------------------------------------
// Causal flash attention on tf32 tensor cores.
// Grid (SS/128, NH, BB), 256 threads (8 warps), q-tile 128 rows, kv-tile 64.
// Warp w owns q rows [w*16, w*16+16). Fragment mapping identical to tf32_gemm
// (empirically verified): thread(g,t) -> acc rows g,g+8; cols 2t,2t+1 per n8.
// SMEM strides: Q/K/V 132, P 68 (all ==4 mod 32 -> conflict-free frag LDS).
// P is warp-private (each warp reads only its own 16 rows) -> no barrier.
// ---------------------------------------------------------------------------
#define QLD 132
#define KLD 132
#define PLD 68
#define ATTN_SMEM ((128 * QLD + 64 * KLD + 128 * PLD) * 4)   // 136192 B

__global__ __launch_bounds__(256)
void attn_tc_kernel(const float* __restrict__ Q, const float* __restrict__ Kg,
                    const float* __restrict__ Vg, float* __restrict__ ctx)
{
    extern __shared__ float smf[];
    float* Qs = smf;                            // [128][132]
    float* Ks = smf + 128 * QLD;                // [64][132], reused for V
    float* Ps = smf + 128 * QLD + 64 * KLD;     // [128][68]

    const int tid  = threadIdx.x;
    const int lane = tid & 31;
    const int w    = tid >> 5;        // warp 0..7 -> q rows w*16..w*16+15
    const int g    = lane >> 2;       // mma groupID 0..7
    const int t    = lane & 3;        // mma thread-in-group 0..3
    const int q0   = blockIdx.x << 7;
    const int h    = blockIdx.y;
    const int b    = blockIdx.z;
    const int gr   = h >> 2;

    // load Q tile (128 x 128)
    for (int f = tid; f < 4096; f += 256) {
        const int r = f >> 5, c = (f & 31) << 2;
        float4 v = *(const float4*)(Q + ((size_t)((b * SS + q0 + r) * NH + h)) * HD + c);
        *(float4*)&Qs[r * QLD + c] = v;
    }

    // softmax state: rows r0 = w*16+g, r1 = r0+8
    float m0 = -1e30f, m1 = -1e30f, l0 = 0.f, l1 = 0.f;
    float O[16][4];
#pragma unroll
    for (int nt = 0; nt < 16; ++nt)
#pragma unroll
        for (int r = 0; r < 4; ++r) O[nt][r] = 0.f;

    const bool mask_any_base = true; (void)mask_any_base;
    const int ntiles = (q0 >> 6) + 2;

    for (int jt = 0; jt < ntiles; ++jt) {
        const int j0 = jt << 6;
        const bool active = (j0 <= q0 + w * 16 + 15);   // else fully masked for this warp

        __syncthreads();    // prior PV reads of Ks done
        for (int f = tid; f < 2048; f += 256) {
            const int r = f >> 5, c = (f & 31) << 2;
            float4 v = *(const float4*)(Kg + ((size_t)((b * SS + j0 + r) * NG + gr)) * HD + c);
            *(float4*)&Ks[r * KLD + c] = v;
        }
        __syncthreads();

        if (active) {
            // ---- S = Q @ K^T (16 x 64 per warp) ----
            float S[8][4];
#pragma unroll
            for (int nt = 0; nt < 8; ++nt)
#pragma unroll
                for (int r = 0; r < 4; ++r) S[nt][r] = 0.f;

#pragma unroll
            for (int ks = 0; ks < 16; ++ks) {
                const int kb = ks * 8 + t;
                uint32_t af[4];
                const int r0 = w * 16 + g;
                af[0] = f2tf32(Qs[r0 * QLD + kb]);
                af[1] = f2tf32(Qs[(r0 + 8) * QLD + kb]);
                af[2] = f2tf32(Qs[r0 * QLD + kb + 4]);
                af[3] = f2tf32(Qs[(r0 + 8) * QLD + kb + 4]);
#pragma unroll
                for (int nt = 0; nt < 8; ++nt) {
                    uint32_t bf[2];
                    bf[0] = f2tf32(Ks[(nt * 8 + g) * KLD + kb]);
                    bf[1] = f2tf32(Ks[(nt * 8 + g) * KLD + kb + 4]);
                    mma1688(S[nt], af, bf);
                }
            }

            // ---- causal mask (only tiles touching the diagonal) ----
            if (j0 + 63 > q0 + w * 16) {
                const int r0g = q0 + w * 16 + g;
#pragma unroll
                for (int nt = 0; nt < 8; ++nt) {
                    const int c0 = j0 + nt * 8 + 2 * t;
                    if (c0     > r0g)     S[nt][0] = -1e30f;
                    if (c0 + 1 > r0g)     S[nt][1] = -1e30f;
                    if (c0     > r0g + 8) S[nt][2] = -1e30f;
                    if (c0 + 1 > r0g + 8) S[nt][3] = -1e30f;
                }
            }

            // ---- online softmax (rows g, g+8; reduce across quad lanes t) ----
            float mx0 = -1e30f, mx1 = -1e30f;
#pragma unroll
            for (int nt = 0; nt < 8; ++nt) {
                mx0 = fmaxf(mx0, fmaxf(S[nt][0], S[nt][1]));
                mx1 = fmaxf(mx1, fmaxf(S[nt][2], S[nt][3]));
            }
#pragma unroll
            for (int o = 1; o <= 2; o <<= 1) {
                mx0 = fmaxf(mx0, __shfl_xor_sync(0xffffffffu, mx0, o));
                mx1 = fmaxf(mx1, __shfl_xor_sync(0xffffffffu, mx1, o));
            }
            const float mn0 = fmaxf(m0, mx0);
            const float mn1 = fmaxf(m1, mx1);
            const float cr0 = __expf(m0 - mn0);
            const float cr1 = __expf(m1 - mn1);
            float rs0 = 0.f, rs1 = 0.f;
#pragma unroll
            for (int nt = 0; nt < 8; ++nt) {
                S[nt][0] = __expf(S[nt][0] - mn0);
                S[nt][1] = __expf(S[nt][1] - mn0);
                S[nt][2] = __expf(S[nt][2] - mn1);
                S[nt][3] = __expf(S[nt][3] - mn1);
                rs0 += S[nt][0] + S[nt][1];
                rs1 += S[nt][2] + S[nt][3];
            }
#pragma unroll
            for (int o = 1; o <= 2; o <<= 1) {
                rs0 += __shfl_xor_sync(0xffffffffu, rs0, o);
                rs1 += __shfl_xor_sync(0xffffffffu, rs1, o);
            }
            l0 = l0 * cr0 + rs0;
            l1 = l1 * cr1 + rs1;
            m0 = mn0; m1 = mn1;
#pragma unroll
            for (int nt = 0; nt < 16; ++nt) {
                O[nt][0] *= cr0; O[nt][1] *= cr0;
                O[nt][2] *= cr1; O[nt][3] *= cr1;
            }
            // store P (warp-private rows -> no cross-warp barrier needed)
            const int pr0 = w * 16 + g;
#pragma unroll
            for (int nt = 0; nt < 8; ++nt) {
                *(float2*)&Ps[pr0 * PLD + nt * 8 + 2 * t]       = make_float2(S[nt][0], S[nt][1]);
                *(float2*)&Ps[(pr0 + 8) * PLD + nt * 8 + 2 * t] = make_float2(S[nt][2], S[nt][3]);
            }
        }

        __syncthreads();    // all K reads done -> safe to overwrite with V
        for (int f = tid; f < 2048; f += 256) {
            const int r = f >> 5, c = (f & 31) << 2;
            float4 v = *(const float4*)(Vg + ((size_t)((b * SS + j0 + r) * NG + gr)) * HD + c);
            *(float4*)&Ks[r * KLD + c] = v;
        }
        __syncthreads();

        if (active) {
            // ---- O += P @ V  (16 x 128 per warp, k = 64) ----
#pragma unroll
            for (int ks = 0; ks < 8; ++ks) {
                const int kb = ks * 8 + t;
                uint32_t pf[4];
                const int r0 = w * 16 + g;
                pf[0] = f2tf32(Ps[r0 * PLD + kb]);
                pf[1] = f2tf32(Ps[(r0 + 8) * PLD + kb]);
                pf[2] = f2tf32(Ps[r0 * PLD + kb + 4]);
                pf[3] = f2tf32(Ps[(r0 + 8) * PLD + kb + 4]);
#pragma unroll
                for (int nt = 0; nt < 16; ++nt) {
                    uint32_t bf[2];
                    bf[0] = f2tf32(Ks[kb * KLD + nt * 8 + g]);
                    bf[1] = f2tf32(Ks[(kb + 4) * KLD + nt * 8 + g]);
                    mma1688(O[nt], pf, bf);
                }
            }
        }
    }

    // ---- normalize + write ctx (b, s, h, hd) ----
    const float inv0 = 1.0f / l0;
    const float inv1 = 1.0f / l1;
    const int r0 = q0 + w * 16 + g;
#pragma unroll
    for (int nt = 0; nt < 16; ++nt) {
        const int col = nt * 8 + 2 * t;
        float* p0 = ctx + ((size_t)((b * SS + r0) * NH + h)) * HD + col;
        float* p1 = ctx + ((size_t)((b * SS + r0 + 8) * NH + h)) * HD + col;
        *(float2*)p0 = make_float2(O[nt][0] * inv0, O[nt][1] * inv0);
        *(float2*)p1 = make_float2(O[nt][2] * inv1, O[nt][3] * inv1);
    }
}

// ---------------------------------------------------------------------------
// kernel_launch
// ---------------------------------------------------------------------------
extern "C" void kernel_launch(void* const* d_in, const int* in_sizes, int n_in,
                              void* d_out, int out_size)
{
    (void)in_sizes; (void)n_in; (void)out_size;
    const float* x  = (const float*)d_in[0];
    const float* Wq = (const float*)d_in[1];
    const float* bq = (const float*)d_in[2];
    const float* Wk = (const float*)d_in[3];
    const float* bk = (const float*)d_in[4];
    const float* Wv = (const float*)d_in[5];
    const float* bv = (const float*)d_in[6];
    const float* Wo = (const float*)d_in[7];
    const float* bo = (const float*)d_in[8];
    const float* q_scale = (const float*)d_in[9];
    const float* k_scale = (const float*)d_in[10];
    float* out = (float*)d_out;

    float *gq, *gk, *gv, *gc;
    cudaGetSymbolAddress((void**)&gq, g_q);
    cudaGetSymbolAddress((void**)&gk, g_k);
    cudaGetSymbolAddress((void**)&gv, g_v);
    cudaGetSymbolAddress((void**)&gc, g_ctx);

    cudaFuncSetAttribute(attn_tc_kernel,
                         cudaFuncAttributeMaxDynamicSharedMemorySize, ATTN_SMEM);

    const dim3 blk(256);

    // Projections (tf32 mma, W used untransposed, 2-stage pipeline = R13 best)
    tf32_gemm<<<dim3(DD / 128, MROWS / 128), blk>>>(x, Wq, bq, gq, MROWS, DD, DD);
    tf32_gemm<<<dim3(KVD / 128, MROWS / 128), blk>>>(x, Wk, bk, gk, MROWS, KVD, DD);
    tf32_gemm<<<dim3(KVD / 128, MROWS / 128), blk>>>(x, Wv, bv, gv, MROWS, KVD, DD);

    // RMSNorm + RoPE (q gets combined 1/hd logit scale folded in)
    norm_rope_kernel<<<(MROWS * NH) / 8, blk>>>(gq, q_scale, NH, 1.0f / 128.0f);
    norm_rope_kernel<<<(MROWS * NG) / 8, blk>>>(gk, k_scale, NG, 1.0f);

    // Causal GQA attention on tensor cores
    attn_tc_kernel<<<dim3(SS / 128, NH, BB), blk, ATTN_SMEM>>>(gq, gk, gv, gc);

    // Output projection
    tf32_gemm<<<dim3(DD / 128, MROWS / 128), blk>>>(gc, Wo, bo, out, MROWS, DD, DD);
}